// round 11
// baseline (speedup 1.0000x reference)
#include <cuda_runtime.h>
#include <cuda_bf16.h>
#include <math.h>
#include <stdint.h>

// Problem constants
constexpr int TOKENS = 4 * 4096;   // 16384
constexpr int D      = 1024;
constexpr int DFF    = 4096;

// ---------------------------------------------------------------------------
// Static device scratch (no allocations allowed) — all fp32 (tf32-rounded)
// ---------------------------------------------------------------------------
__device__ float g_tmp [(size_t)TOKENS * D];        // LN output (reused for LN2)
__device__ float g_qkv [(size_t)TOKENS * 3 * D];    // q|k|v per token
__device__ float g_attn[(size_t)TOKENS * D];        // attention output
__device__ float g_x2  [(size_t)TOKENS * D];        // x + attn@Wo + bo (exact fp32)
__device__ float g_ff  [(size_t)TOKENS * DFF];      // gelu(tmp@W1+b1)
__device__ float g_wqkv[(size_t)3 * D * D];         // [3D, D]  (N,K layout)
__device__ float g_wo  [(size_t)D * D];             // [D, D]
__device__ float g_w1  [(size_t)DFF * D];           // [DFF, D]
__device__ float g_w2  [(size_t)D * DFF];           // [D, DFF]

// ---------------------------------------------------------------------------
// PTX helpers
// ---------------------------------------------------------------------------
__device__ __forceinline__ float tf32r(float x) {
    asm("cvt.rna.tf32.f32 %0, %1;\n" : "=f"(x) : "f"(x));
    return x;
}

__device__ __forceinline__ void mma_tf32(float c[4], uint32_t a0, uint32_t a1,
                                         uint32_t a2, uint32_t a3,
                                         uint32_t b0, uint32_t b1) {
    asm volatile(
        "mma.sync.aligned.m16n8k8.row.col.f32.tf32.tf32.f32 "
        "{%0,%1,%2,%3}, {%4,%5,%6,%7}, {%8,%9}, {%0,%1,%2,%3};\n"
        : "+f"(c[0]), "+f"(c[1]), "+f"(c[2]), "+f"(c[3])
        : "r"(a0), "r"(a1), "r"(a2), "r"(a3), "r"(b0), "r"(b1));
}

// ldmatrix.x4: four 8x8 b16 tiles == four 8x4 tf32 tiles; lane l owns tf32
// element (l/4, l%4) of its tile — exactly the m16n8k8 tf32 A/B fragment map
// (validated R8/R9: bit-identical output).
__device__ __forceinline__ void ldsm4(uint32_t r[4], const float* p) {
    uint32_t a = (uint32_t)__cvta_generic_to_shared(p);
    asm volatile("ldmatrix.sync.aligned.m8n8.x4.shared.b16 {%0,%1,%2,%3}, [%4];\n"
                 : "=r"(r[0]), "=r"(r[1]), "=r"(r[2]), "=r"(r[3]) : "r"(a));
}

__device__ __forceinline__ void cpa16(const void* smem, const void* gmem) {
    uint32_t a = (uint32_t)__cvta_generic_to_shared(smem);
    asm volatile("cp.async.cg.shared.global [%0], [%1], 16;\n" :: "r"(a), "l"(gmem) : "memory");
}
#define CP_COMMIT() asm volatile("cp.async.commit_group;\n" ::: "memory")

// ---------------------------------------------------------------------------
// Weight transpose + tf32 rounding:  W[K,N] fp32 -> Wt[N,K] fp32(tf32)
// ---------------------------------------------------------------------------
__global__ void transpose_cvt(const float* __restrict__ W, float* __restrict__ Wt,
                              int K, int N) {
    __shared__ float t[32][33];
    int n0 = blockIdx.x * 32, k0 = blockIdx.y * 32;
    #pragma unroll
    for (int r = threadIdx.y; r < 32; r += 8)
        t[r][threadIdx.x] = W[(size_t)(k0 + r) * N + n0 + threadIdx.x];
    __syncthreads();
    #pragma unroll
    for (int r = threadIdx.y; r < 32; r += 8)
        Wt[(size_t)(n0 + r) * K + k0 + threadIdx.x] = tf32r(t[threadIdx.x][r]);
}

// ---------------------------------------------------------------------------
// LayerNorm (fp32 in -> fp32(tf32) out), one block per row of 1024
// ---------------------------------------------------------------------------
__global__ void __launch_bounds__(256) ln_kernel(const float* __restrict__ x,
                                                 const float* __restrict__ g,
                                                 const float* __restrict__ b,
                                                 float* __restrict__ out) {
    const int row = blockIdx.x;
    const int tid = threadIdx.x;
    const float4 v = reinterpret_cast<const float4*>(x + (size_t)row * D)[tid];
    float s  = v.x + v.y + v.z + v.w;
    float ss = v.x * v.x + v.y * v.y + v.z * v.z + v.w * v.w;
    #pragma unroll
    for (int o = 16; o; o >>= 1) {
        s  += __shfl_xor_sync(0xffffffffu, s, o);
        ss += __shfl_xor_sync(0xffffffffu, ss, o);
    }
    __shared__ float sh[16];
    const int warp = tid >> 5, lane = tid & 31;
    if (lane == 0) { sh[warp] = s; sh[warp + 8] = ss; }
    __syncthreads();
    float ts = 0.f, tss = 0.f;
    #pragma unroll
    for (int w = 0; w < 8; ++w) { ts += sh[w]; tss += sh[w + 8]; }
    const float mu = ts * (1.0f / D);
    const float var = tss * (1.0f / D) - mu * mu;
    const float rs = rsqrtf(var + 1e-5f);
    const float4 gg = reinterpret_cast<const float4*>(g)[tid];
    const float4 bb = reinterpret_cast<const float4*>(b)[tid];
    float4 o;
    o.x = tf32r((v.x - mu) * rs * gg.x + bb.x);
    o.y = tf32r((v.y - mu) * rs * gg.y + bb.y);
    o.z = tf32r((v.z - mu) * rs * gg.z + bb.z);
    o.w = tf32r((v.w - mu) * rs * gg.w + bb.w);
    reinterpret_cast<float4*>(out + (size_t)row * D)[tid] = o;
}

// ---------------------------------------------------------------------------
// Per-token head-mixing attention (fp32 in -> fp32(tf32) out).
// ---------------------------------------------------------------------------
__global__ void __launch_bounds__(64) attn_kernel(const float* __restrict__ qkv,
                                                  const float* __restrict__ unc,
                                                  float* __restrict__ out) {
    const int tok = blockIdx.x;
    const int i = threadIdx.x;
    __shared__ float ks[16][64];
    __shared__ float vs[16][64];
    const float* base = qkv + (size_t)tok * (3 * D);

    float qi[16];
    #pragma unroll
    for (int h = 0; h < 16; ++h) {
        ks[h][i] = base[D + h * 64 + i];
        vs[h][i] = base[2 * D + h * 64 + i];
        qi[h] = base[h * 64 + i];
    }
    float su = 0.f;
    #pragma unroll
    for (int h = 0; h < 16; ++h) su += unc[h];
    const float iscale = 1.0f / (8.0f * su);
    __syncthreads();

    float s[64];
    #pragma unroll
    for (int j = 0; j < 64; ++j) s[j] = 0.f;
    #pragma unroll
    for (int h = 0; h < 16; ++h) {
        const float qh = qi[h];
        const float4* kr = reinterpret_cast<const float4*>(&ks[h][0]);
        #pragma unroll
        for (int j4 = 0; j4 < 16; ++j4) {
            const float4 kv = kr[j4];
            s[j4 * 4 + 0] += qh * kv.x;
            s[j4 * 4 + 1] += qh * kv.y;
            s[j4 * 4 + 2] += qh * kv.z;
            s[j4 * 4 + 3] += qh * kv.w;
        }
    }
    float m = -1e30f;
    #pragma unroll
    for (int j = 0; j < 64; ++j) { s[j] *= iscale; m = fmaxf(m, s[j]); }
    float den = 0.f;
    #pragma unroll
    for (int j = 0; j < 64; ++j) { s[j] = expf(s[j] - m); den += s[j]; }
    const float dinv = 1.0f / den;

    float* ob = out + (size_t)tok * D;
    #pragma unroll
    for (int h = 0; h < 16; ++h) {
        const float4* vr = reinterpret_cast<const float4*>(&vs[h][0]);
        float o = 0.f;
        #pragma unroll
        for (int j4 = 0; j4 < 16; ++j4) {
            const float4 vv = vr[j4];
            o += s[j4 * 4 + 0] * vv.x + s[j4 * 4 + 1] * vv.y +
                 s[j4 * 4 + 2] * vv.z + s[j4 * 4 + 3] * vv.w;
        }
        ob[h * 64 + i] = tf32r(o * dinv);
    }
}

// ---------------------------------------------------------------------------
// Tiled TF32 GEMM: C[M,N] = A[M,K] @ Bt[N,K]^T with epilogues.
// BM=128, BN=128, BK=32, 2-stage cp.async (dynamic smem, 72KB), 256 threads
// (8 warps as 2x4, warp tile 64x32), ldmatrix.x4 fragment loads.
// __launch_bounds__(256, 2): force <=128 regs so 2 CTAs/SM stay resident —
// cross-CTA overlap hides the per-k-step __syncthreads + load latency.
// EPI 0: out fp32(tf32) = C
// EPI 1: out fp32       = C + bias + res     (exact residual path)
// EPI 2: out fp32(tf32) = gelu(C + bias)     (exact erf gelu)
// ---------------------------------------------------------------------------
constexpr int BM = 128, BN = 128, BK = 32, SROW = 36;  // 36r mod 32 = 4r: bank-conflict-free
constexpr int A_ELE = BM * SROW;                        // floats per A stage
constexpr int B_ELE = BN * SROW;
constexpr size_t GEMM_SMEM = (size_t)2 * (A_ELE + B_ELE) * 4;  // 73728 B

template <int EPI>
__global__ void __launch_bounds__(256, 2) gemm_tf32(
    const float* __restrict__ A, const float* __restrict__ Bt,
    const float* __restrict__ bias, const float* __restrict__ res,
    float* __restrict__ out, int M, int N, int K) {
    extern __shared__ float sm[];
    float* As = sm;                  // [2][BM][SROW]
    float* Bs = sm + 2 * A_ELE;      // [2][BN][SROW]

    const int tid = threadIdx.x;
    const int lane = tid & 31;
    const int warp = tid >> 5;
    const int wr = warp >> 2;       // 0..1 (M)
    const int wc = warp & 3;        // 0..3 (N)
    const int bm = blockIdx.y * BM;
    const int bn = blockIdx.x * BN;
    const int g = lane >> 2;        // 0..7
    const int t = lane & 3;         // 0..3

    // cp.async mapping: thread handles row=tid/2, 16-float half (4 chunks)
    const int lrow = tid >> 1;
    const int lc0 = (tid & 1) * 16;
    const float* Ag = A + (size_t)(bm + lrow) * K + lc0;
    const float* Bg = Bt + (size_t)(bn + lrow) * K + lc0;
    float* AsRow = As + lrow * SROW + lc0;
    float* BsRow = Bs + lrow * SROW + lc0;

    // ldmatrix per-lane tile offsets (within 16-row x 8-col region)
    const int a_r = lane & 15;             // rows 0..15
    const int a_c = (lane >> 4) * 4;       // col 0 or 4
    const int b_r = ((lane >> 4) & 1) * 8 + (lane & 7);
    const int b_c = ((lane >> 3) & 1) * 4;
    const float* Afrag = As + (size_t)(wr * 64 + a_r) * SROW + a_c;
    const float* Bfrag = Bs + (size_t)(wc * 32 + b_r) * SROW + b_c;

    float acc[4][4][4];
    #pragma unroll
    for (int i = 0; i < 4; ++i)
        #pragma unroll
        for (int j = 0; j < 4; ++j)
            #pragma unroll
            for (int k = 0; k < 4; ++k) acc[i][j][k] = 0.f;

    auto load_stage = [&](int buf, int kt) {
        const float* a = Ag + kt * BK;
        float* as = AsRow + buf * A_ELE;
        cpa16(as + 0, a + 0);  cpa16(as + 4, a + 4);
        cpa16(as + 8, a + 8);  cpa16(as + 12, a + 12);
        const float* b = Bg + kt * BK;
        float* bs = BsRow + buf * B_ELE;
        cpa16(bs + 0, b + 0);  cpa16(bs + 4, b + 4);
        cpa16(bs + 8, b + 8);  cpa16(bs + 12, b + 12);
    };

    load_stage(0, 0);
    CP_COMMIT();
    const int KT = K / BK;
    for (int kt = 0; kt < KT; ++kt) {
        const int buf = kt & 1;
        if (kt + 1 < KT) {
            load_stage(buf ^ 1, kt + 1);
            CP_COMMIT();
            asm volatile("cp.async.wait_group 1;\n" ::: "memory");
        } else {
            asm volatile("cp.async.wait_group 0;\n" ::: "memory");
        }
        __syncthreads();

        #pragma unroll
        for (int kk = 0; kk < 4; ++kk) {     // four k8 chunks in BK=32
            const float* Ab = Afrag + (size_t)buf * A_ELE + kk * 8;
            const float* Bb = Bfrag + (size_t)buf * B_ELE + kk * 8;
            uint32_t af[4][4];
            #pragma unroll
            for (int mi = 0; mi < 4; ++mi)
                ldsm4(af[mi], Ab + (size_t)mi * 16 * SROW);
            uint32_t bfr[2][4];
            #pragma unroll
            for (int nj = 0; nj < 2; ++nj)
                ldsm4(bfr[nj], Bb + (size_t)nj * 16 * SROW);
            #pragma unroll
            for (int mi = 0; mi < 4; ++mi)
                #pragma unroll
                for (int ni = 0; ni < 4; ++ni)
                    mma_tf32(acc[mi][ni], af[mi][0], af[mi][1], af[mi][2], af[mi][3],
                             bfr[ni >> 1][(ni & 1) * 2], bfr[ni >> 1][(ni & 1) * 2 + 1]);
        }
        __syncthreads();
    }

    // Epilogue
    #pragma unroll
    for (int mi = 0; mi < 4; ++mi) {
        #pragma unroll
        for (int ni = 0; ni < 4; ++ni) {
            const int row = bm + wr * 64 + mi * 16 + g;
            const int col = bn + wc * 32 + ni * 8 + t * 2;
            const float c0 = acc[mi][ni][0], c1 = acc[mi][ni][1];
            const float c2 = acc[mi][ni][2], c3 = acc[mi][ni][3];
            if (EPI == 0) {
                *(float2*)(out + (size_t)row * N + col) =
                    make_float2(tf32r(c0), tf32r(c1));
                *(float2*)(out + (size_t)(row + 8) * N + col) =
                    make_float2(tf32r(c2), tf32r(c3));
            } else if (EPI == 1) {
                const float bz0 = bias[col], bz1 = bias[col + 1];
                const float* r0 = res + (size_t)row * N + col;
                const float* r1 = res + (size_t)(row + 8) * N + col;
                *(float2*)(out + (size_t)row * N + col) =
                    make_float2(c0 + bz0 + r0[0], c1 + bz1 + r0[1]);
                *(float2*)(out + (size_t)(row + 8) * N + col) =
                    make_float2(c2 + bz0 + r1[0], c3 + bz1 + r1[1]);
            } else {
                const float bz0 = bias[col], bz1 = bias[col + 1];
                auto gelu = [](float v) { return 0.5f * v * (1.0f + erff(v * 0.70710678118654752f)); };
                *(float2*)(out + (size_t)row * N + col) =
                    make_float2(tf32r(gelu(c0 + bz0)), tf32r(gelu(c1 + bz1)));
                *(float2*)(out + (size_t)(row + 8) * N + col) =
                    make_float2(tf32r(gelu(c2 + bz0)), tf32r(gelu(c3 + bz1)));
            }
        }
    }
}

// ---------------------------------------------------------------------------
// Launch
// ---------------------------------------------------------------------------
extern "C" void kernel_launch(void* const* d_in, const int* in_sizes, int n_in,
                              void* d_out, int out_size) {
    const float* x    = (const float*)d_in[0];
    const float* unc  = (const float*)d_in[1];
    const float* Wq   = (const float*)d_in[2];
    const float* Wk   = (const float*)d_in[3];
    const float* Wv   = (const float*)d_in[4];
    const float* Wo   = (const float*)d_in[5];
    const float* bo   = (const float*)d_in[6];
    const float* ln1g = (const float*)d_in[7];
    const float* ln1b = (const float*)d_in[8];
    const float* ln2g = (const float*)d_in[9];
    const float* ln2b = (const float*)d_in[10];
    const float* W1   = (const float*)d_in[11];
    const float* b1   = (const float*)d_in[12];
    const float* W2   = (const float*)d_in[13];
    const float* b2   = (const float*)d_in[14];

    float *tmp, *qkv, *attn, *x2, *ff, *wqkv, *wo, *w1, *w2;
    cudaGetSymbolAddress((void**)&tmp, g_tmp);
    cudaGetSymbolAddress((void**)&qkv, g_qkv);
    cudaGetSymbolAddress((void**)&attn, g_attn);
    cudaGetSymbolAddress((void**)&x2, g_x2);
    cudaGetSymbolAddress((void**)&ff, g_ff);
    cudaGetSymbolAddress((void**)&wqkv, g_wqkv);
    cudaGetSymbolAddress((void**)&wo, g_wo);
    cudaGetSymbolAddress((void**)&w1, g_w1);
    cudaGetSymbolAddress((void**)&w2, g_w2);

    cudaFuncSetAttribute(gemm_tf32<0>, cudaFuncAttributeMaxDynamicSharedMemorySize, (int)GEMM_SMEM);
    cudaFuncSetAttribute(gemm_tf32<1>, cudaFuncAttributeMaxDynamicSharedMemorySize, (int)GEMM_SMEM);
    cudaFuncSetAttribute(gemm_tf32<2>, cudaFuncAttributeMaxDynamicSharedMemorySize, (int)GEMM_SMEM);

    const dim3 tb(32, 8);
    transpose_cvt<<<dim3(D / 32, D / 32), tb>>>(Wq, wqkv, D, D);
    transpose_cvt<<<dim3(D / 32, D / 32), tb>>>(Wk, wqkv + (size_t)D * D, D, D);
    transpose_cvt<<<dim3(D / 32, D / 32), tb>>>(Wv, wqkv + (size_t)2 * D * D, D, D);
    transpose_cvt<<<dim3(D / 32, D / 32), tb>>>(Wo, wo, D, D);
    transpose_cvt<<<dim3(DFF / 32, D / 32), tb>>>(W1, w1, D, DFF);
    transpose_cvt<<<dim3(D / 32, DFF / 32), tb>>>(W2, w2, DFF, D);

    // tmp = LN1(x)
    ln_kernel<<<TOKENS, 256>>>(x, ln1g, ln1b, tmp);
    // qkv = tmp @ [Wq|Wk|Wv]
    gemm_tf32<0><<<dim3(3 * D / BN, TOKENS / BM), 256, GEMM_SMEM>>>(
        tmp, wqkv, nullptr, nullptr, qkv, TOKENS, 3 * D, D);
    // per-token attention
    attn_kernel<<<TOKENS, 64>>>(qkv, unc, attn);
    // x2 = x + attn @ Wo + bo
    gemm_tf32<1><<<dim3(D / BN, TOKENS / BM), 256, GEMM_SMEM>>>(
        attn, wo, bo, x, x2, TOKENS, D, D);
    // tmp = LN2(x2)
    ln_kernel<<<TOKENS, 256>>>(x2, ln2g, ln2b, tmp);
    // ff = gelu(tmp @ W1 + b1)
    gemm_tf32<2><<<dim3(DFF / BN, TOKENS / BM), 256, GEMM_SMEM>>>(
        tmp, w1, b1, nullptr, ff, TOKENS, DFF, D);
    // out = x2 + ff @ W2 + b2
    gemm_tf32<1><<<dim3(D / BN, TOKENS / BM), 256, GEMM_SMEM>>>(
        ff, w2, b2, x2, (float*)d_out, TOKENS, D, DFF);
}

// round 13
// speedup vs baseline: 1.8609x; 1.8609x over previous
#include <cuda_runtime.h>
#include <cuda_fp16.h>
#include <math.h>
#include <stdint.h>

using f16 = __half;

// Problem constants
constexpr int TOKENS = 4 * 4096;   // 16384
constexpr int D      = 1024;
constexpr int DFF    = 4096;

// ---------------------------------------------------------------------------
// Static device scratch — activations fp16, residual path exact fp32
// ---------------------------------------------------------------------------
__device__ f16   g_tmp [(size_t)TOKENS * D];        // LN output (reused for LN2)
__device__ f16   g_qkv [(size_t)TOKENS * 3 * D];    // q|k|v per token
__device__ f16   g_attn[(size_t)TOKENS * D];        // attention output
__device__ float g_x2  [(size_t)TOKENS * D];        // x + attn@Wo + bo (exact fp32)
__device__ f16   g_ff  [(size_t)TOKENS * DFF];      // gelu(tmp@W1+b1)
__device__ f16   g_wqkv[(size_t)3 * D * D];         // [3D, D]  (N,K layout)
__device__ f16   g_wo  [(size_t)D * D];
__device__ f16   g_w1  [(size_t)DFF * D];
__device__ f16   g_w2  [(size_t)D * DFF];

// ---------------------------------------------------------------------------
// PTX helpers
// ---------------------------------------------------------------------------
__device__ __forceinline__ void ldsm4(uint32_t& r0, uint32_t& r1, uint32_t& r2,
                                      uint32_t& r3, const void* p) {
    uint32_t a = (uint32_t)__cvta_generic_to_shared(p);
    asm volatile("ldmatrix.sync.aligned.m8n8.x4.shared.b16 {%0,%1,%2,%3}, [%4];\n"
                 : "=r"(r0), "=r"(r1), "=r"(r2), "=r"(r3) : "r"(a));
}

__device__ __forceinline__ void mma16816(float c[4], uint32_t a0, uint32_t a1,
                                         uint32_t a2, uint32_t a3,
                                         uint32_t b0, uint32_t b1) {
    asm volatile(
        "mma.sync.aligned.m16n8k16.row.col.f32.f16.f16.f32 "
        "{%0,%1,%2,%3}, {%4,%5,%6,%7}, {%8,%9}, {%0,%1,%2,%3};\n"
        : "+f"(c[0]), "+f"(c[1]), "+f"(c[2]), "+f"(c[3])
        : "r"(a0), "r"(a1), "r"(a2), "r"(a3), "r"(b0), "r"(b1));
}

__device__ __forceinline__ void cpa16(const void* smem, const void* gmem) {
    uint32_t a = (uint32_t)__cvta_generic_to_shared(smem);
    asm volatile("cp.async.cg.shared.global [%0], [%1], 16;\n" :: "r"(a), "l"(gmem) : "memory");
}
#define CP_COMMIT() asm volatile("cp.async.commit_group;\n" ::: "memory")

// ---------------------------------------------------------------------------
// Weight transpose + fp32->fp16 convert:  W[K,N] -> Wt[N,K]
// ---------------------------------------------------------------------------
__global__ void transpose_cvt(const float* __restrict__ W, f16* __restrict__ Wt,
                              int K, int N) {
    __shared__ float t[32][33];
    int n0 = blockIdx.x * 32, k0 = blockIdx.y * 32;
    #pragma unroll
    for (int r = threadIdx.y; r < 32; r += 8)
        t[r][threadIdx.x] = W[(size_t)(k0 + r) * N + n0 + threadIdx.x];
    __syncthreads();
    #pragma unroll
    for (int r = threadIdx.y; r < 32; r += 8)
        Wt[(size_t)(n0 + r) * K + k0 + threadIdx.x] = __float2half_rn(t[threadIdx.x][r]);
}

// ---------------------------------------------------------------------------
// LayerNorm (fp32 in -> fp16 out), one block per row of 1024
// ---------------------------------------------------------------------------
__global__ void __launch_bounds__(256) ln_kernel(const float* __restrict__ x,
                                                 const float* __restrict__ g,
                                                 const float* __restrict__ b,
                                                 f16* __restrict__ out) {
    const int row = blockIdx.x;
    const int tid = threadIdx.x;
    const float4 v = reinterpret_cast<const float4*>(x + (size_t)row * D)[tid];
    float s  = v.x + v.y + v.z + v.w;
    float ss = v.x * v.x + v.y * v.y + v.z * v.z + v.w * v.w;
    #pragma unroll
    for (int o = 16; o; o >>= 1) {
        s  += __shfl_xor_sync(0xffffffffu, s, o);
        ss += __shfl_xor_sync(0xffffffffu, ss, o);
    }
    __shared__ float sh[16];
    const int warp = tid >> 5, lane = tid & 31;
    if (lane == 0) { sh[warp] = s; sh[warp + 8] = ss; }
    __syncthreads();
    float ts = 0.f, tss = 0.f;
    #pragma unroll
    for (int w = 0; w < 8; ++w) { ts += sh[w]; tss += sh[w + 8]; }
    const float mu = ts * (1.0f / D);
    const float var = tss * (1.0f / D) - mu * mu;
    const float rs = rsqrtf(var + 1e-5f);
    const float4 gg = reinterpret_cast<const float4*>(g)[tid];
    const float4 bb = reinterpret_cast<const float4*>(b)[tid];
    __half2* o2 = reinterpret_cast<__half2*>(out + (size_t)row * D);
    o2[tid * 2 + 0] = __floats2half2_rn((v.x - mu) * rs * gg.x + bb.x,
                                        (v.y - mu) * rs * gg.y + bb.y);
    o2[tid * 2 + 1] = __floats2half2_rn((v.z - mu) * rs * gg.z + bb.z,
                                        (v.w - mu) * rs * gg.w + bb.w);
}

// ---------------------------------------------------------------------------
// Per-token head-mixing attention (fp16 in -> fp16 out, fp32 math).
// q[i,h] = qkv[tok, h*64+i]; scores[i,j] = sum_h q[i,h]k[j,h] / (8*sum(unc));
// out[tok, h*64+i] = sum_j softmax(scores)[i,j] * v[j,h]
// One block per token, 64 threads: thread i owns scores row i.
// ---------------------------------------------------------------------------
__global__ void __launch_bounds__(64) attn_kernel(const f16* __restrict__ qkv,
                                                  const float* __restrict__ unc,
                                                  f16* __restrict__ out) {
    const int tok = blockIdx.x;
    const int i = threadIdx.x;
    __shared__ float ks[16][64];
    __shared__ float vs[16][64];
    const f16* base = qkv + (size_t)tok * (3 * D);

    float qi[16];
    #pragma unroll
    for (int h = 0; h < 16; ++h) {
        ks[h][i] = __half2float(base[D + h * 64 + i]);
        vs[h][i] = __half2float(base[2 * D + h * 64 + i]);
        qi[h] = __half2float(base[h * 64 + i]);
    }
    float su = 0.f;
    #pragma unroll
    for (int h = 0; h < 16; ++h) su += unc[h];
    const float iscale = 1.0f / (8.0f * su);
    __syncthreads();

    float s[64];
    #pragma unroll
    for (int j = 0; j < 64; ++j) s[j] = 0.f;
    #pragma unroll
    for (int h = 0; h < 16; ++h) {
        const float qh = qi[h];
        const float4* kr = reinterpret_cast<const float4*>(&ks[h][0]);
        #pragma unroll
        for (int j4 = 0; j4 < 16; ++j4) {
            const float4 kv = kr[j4];
            s[j4 * 4 + 0] += qh * kv.x;
            s[j4 * 4 + 1] += qh * kv.y;
            s[j4 * 4 + 2] += qh * kv.z;
            s[j4 * 4 + 3] += qh * kv.w;
        }
    }
    float m = -1e30f;
    #pragma unroll
    for (int j = 0; j < 64; ++j) { s[j] *= iscale; m = fmaxf(m, s[j]); }
    float den = 0.f;
    #pragma unroll
    for (int j = 0; j < 64; ++j) { s[j] = expf(s[j] - m); den += s[j]; }
    const float dinv = 1.0f / den;

    f16* ob = out + (size_t)tok * D;
    #pragma unroll
    for (int h = 0; h < 16; ++h) {
        const float4* vr = reinterpret_cast<const float4*>(&vs[h][0]);
        float o = 0.f;
        #pragma unroll
        for (int j4 = 0; j4 < 16; ++j4) {
            const float4 vv = vr[j4];
            o += s[j4 * 4 + 0] * vv.x + s[j4 * 4 + 1] * vv.y +
                 s[j4 * 4 + 2] * vv.z + s[j4 * 4 + 3] * vv.w;
        }
        ob[h * 64 + i] = __float2half_rn(o * dinv);
    }
}

// ---------------------------------------------------------------------------
// Tiled FP16 GEMM (fp32 accum): C[M,N] = A[M,K] @ Bt[N,K]^T with epilogues.
// R1-validated structure: BM=128, BN=128, BK=32 halves, 2-stage cp.async,
// 256 threads (8 warps as 2x4, warp tile 64x32), ldmatrix.x4 + m16n8k16.
// EPI 0: out fp16 = C
// EPI 1: out fp32 = C + bias + res     (exact residual path)
// EPI 2: out fp16 = gelu(C + bias)     (exact erf gelu)
// ---------------------------------------------------------------------------
constexpr int BM = 128, BN = 128, BK = 32, PAD = 8;

template <int EPI>
__global__ void __launch_bounds__(256) gemm_f16(
    const f16* __restrict__ A, const f16* __restrict__ Bt,
    const float* __restrict__ bias, const float* __restrict__ res,
    void* __restrict__ out, int M, int N, int K) {
    __shared__ f16 As[2][BM][BK + PAD];
    __shared__ f16 Bs[2][BN][BK + PAD];

    const int tid = threadIdx.x;
    const int lane = tid & 31;
    const int warp = tid >> 5;
    const int wr = warp >> 2;       // 0..1 (M)
    const int wc = warp & 3;        // 0..3 (N)
    const int bm = blockIdx.y * BM;
    const int bn = blockIdx.x * BN;

    // cp.async mapping: each thread loads one row-half (16 halves = 2x16B)
    const int lrow = tid >> 1;
    const int lch = (tid & 1) * 16;
    const f16* Ag = A + (size_t)(bm + lrow) * K + lch;
    const f16* Bg = Bt + (size_t)(bn + lrow) * K + lch;

    float acc[4][4][4];
    #pragma unroll
    for (int i = 0; i < 4; ++i)
        #pragma unroll
        for (int j = 0; j < 4; ++j)
            #pragma unroll
            for (int k = 0; k < 4; ++k) acc[i][j][k] = 0.f;

    auto load_stage = [&](int buf, int kt) {
        const f16* a = Ag + kt * BK;
        cpa16(&As[buf][lrow][lch], a);
        cpa16(&As[buf][lrow][lch + 8], a + 8);
        const f16* b = Bg + kt * BK;
        cpa16(&Bs[buf][lrow][lch], b);
        cpa16(&Bs[buf][lrow][lch + 8], b + 8);
    };

    load_stage(0, 0);
    CP_COMMIT();
    const int KT = K / BK;
    for (int kt = 0; kt < KT; ++kt) {
        const int buf = kt & 1;
        if (kt + 1 < KT) {
            load_stage(buf ^ 1, kt + 1);
            CP_COMMIT();
            asm volatile("cp.async.wait_group 1;\n" ::: "memory");
        } else {
            asm volatile("cp.async.wait_group 0;\n" ::: "memory");
        }
        __syncthreads();

        #pragma unroll
        for (int kk = 0; kk < 2; ++kk) {     // two k16 chunks in BK=32
            uint32_t af[4][4];
            #pragma unroll
            for (int mi = 0; mi < 4; ++mi) {
                const int r = wr * 64 + mi * 16 + (lane & 15);
                const int c = kk * 16 + (lane >> 4) * 8;
                ldsm4(af[mi][0], af[mi][1], af[mi][2], af[mi][3], &As[buf][r][c]);
            }
            uint32_t bfr[2][4];
            #pragma unroll
            for (int nj = 0; nj < 2; ++nj) {  // covers n-tiles 2nj, 2nj+1
                const int l8 = lane & 7;
                const int q = lane >> 3;      // 0..3
                const int n = wc * 32 + nj * 16 + (q >> 1) * 8 + l8;
                const int c = kk * 16 + (q & 1) * 8;
                ldsm4(bfr[nj][0], bfr[nj][1], bfr[nj][2], bfr[nj][3], &Bs[buf][n][c]);
            }
            #pragma unroll
            for (int mi = 0; mi < 4; ++mi)
                #pragma unroll
                for (int ni = 0; ni < 4; ++ni)
                    mma16816(acc[mi][ni], af[mi][0], af[mi][1], af[mi][2], af[mi][3],
                             bfr[ni >> 1][(ni & 1) * 2], bfr[ni >> 1][(ni & 1) * 2 + 1]);
        }
        __syncthreads();
    }

    // Epilogue
    #pragma unroll
    for (int mi = 0; mi < 4; ++mi) {
        #pragma unroll
        for (int ni = 0; ni < 4; ++ni) {
            const int row = bm + wr * 64 + mi * 16 + (lane >> 2);
            const int col = bn + wc * 32 + ni * 8 + (lane & 3) * 2;
            const float c0 = acc[mi][ni][0], c1 = acc[mi][ni][1];
            const float c2 = acc[mi][ni][2], c3 = acc[mi][ni][3];
            if (EPI == 0) {
                f16* o = (f16*)out;
                *(__half2*)(o + (size_t)row * N + col) = __floats2half2_rn(c0, c1);
                *(__half2*)(o + (size_t)(row + 8) * N + col) = __floats2half2_rn(c2, c3);
            } else if (EPI == 1) {
                const float bz0 = bias[col], bz1 = bias[col + 1];
                const float* r0 = res + (size_t)row * N + col;
                const float* r1 = res + (size_t)(row + 8) * N + col;
                float* o = (float*)out;
                *(float2*)(o + (size_t)row * N + col) =
                    make_float2(c0 + bz0 + r0[0], c1 + bz1 + r0[1]);
                *(float2*)(o + (size_t)(row + 8) * N + col) =
                    make_float2(c2 + bz0 + r1[0], c3 + bz1 + r1[1]);
            } else {
                const float bz0 = bias[col], bz1 = bias[col + 1];
                auto gelu = [](float v) { return 0.5f * v * (1.0f + erff(v * 0.70710678118654752f)); };
                f16* o = (f16*)out;
                *(__half2*)(o + (size_t)row * N + col) =
                    __floats2half2_rn(gelu(c0 + bz0), gelu(c1 + bz1));
                *(__half2*)(o + (size_t)(row + 8) * N + col) =
                    __floats2half2_rn(gelu(c2 + bz0), gelu(c3 + bz1));
            }
        }
    }
}

// ---------------------------------------------------------------------------
// Launch
// ---------------------------------------------------------------------------
extern "C" void kernel_launch(void* const* d_in, const int* in_sizes, int n_in,
                              void* d_out, int out_size) {
    const float* x    = (const float*)d_in[0];
    const float* unc  = (const float*)d_in[1];
    const float* Wq   = (const float*)d_in[2];
    const float* Wk   = (const float*)d_in[3];
    const float* Wv   = (const float*)d_in[4];
    const float* Wo   = (const float*)d_in[5];
    const float* bo   = (const float*)d_in[6];
    const float* ln1g = (const float*)d_in[7];
    const float* ln1b = (const float*)d_in[8];
    const float* ln2g = (const float*)d_in[9];
    const float* ln2b = (const float*)d_in[10];
    const float* W1   = (const float*)d_in[11];
    const float* b1   = (const float*)d_in[12];
    const float* W2   = (const float*)d_in[13];
    const float* b2   = (const float*)d_in[14];

    f16 *tmp, *qkv, *attn, *ff, *wqkv, *wo, *w1, *w2;
    float* x2;
    cudaGetSymbolAddress((void**)&tmp, g_tmp);
    cudaGetSymbolAddress((void**)&qkv, g_qkv);
    cudaGetSymbolAddress((void**)&attn, g_attn);
    cudaGetSymbolAddress((void**)&x2, g_x2);
    cudaGetSymbolAddress((void**)&ff, g_ff);
    cudaGetSymbolAddress((void**)&wqkv, g_wqkv);
    cudaGetSymbolAddress((void**)&wo, g_wo);
    cudaGetSymbolAddress((void**)&w1, g_w1);
    cudaGetSymbolAddress((void**)&w2, g_w2);

    const dim3 tb(32, 8);
    transpose_cvt<<<dim3(D / 32, D / 32), tb>>>(Wq, wqkv, D, D);
    transpose_cvt<<<dim3(D / 32, D / 32), tb>>>(Wk, wqkv + (size_t)D * D, D, D);
    transpose_cvt<<<dim3(D / 32, D / 32), tb>>>(Wv, wqkv + (size_t)2 * D * D, D, D);
    transpose_cvt<<<dim3(D / 32, D / 32), tb>>>(Wo, wo, D, D);
    transpose_cvt<<<dim3(DFF / 32, D / 32), tb>>>(W1, w1, D, DFF);
    transpose_cvt<<<dim3(D / 32, DFF / 32), tb>>>(W2, w2, DFF, D);

    // tmp = LN1(x)
    ln_kernel<<<TOKENS, 256>>>(x, ln1g, ln1b, tmp);
    // qkv = tmp @ [Wq|Wk|Wv]
    gemm_f16<0><<<dim3(3 * D / BN, TOKENS / BM), 256>>>(
        tmp, wqkv, nullptr, nullptr, qkv, TOKENS, 3 * D, D);
    // per-token attention
    attn_kernel<<<TOKENS, 64>>>(qkv, unc, attn);
    // x2 = x + attn @ Wo + bo
    gemm_f16<1><<<dim3(D / BN, TOKENS / BM), 256>>>(
        attn, wo, bo, x, x2, TOKENS, D, D);
    // tmp = LN2(x2)
    ln_kernel<<<TOKENS, 256>>>(x2, ln2g, ln2b, tmp);
    // ff = gelu(tmp @ W1 + b1)
    gemm_f16<2><<<dim3(DFF / BN, TOKENS / BM), 256>>>(
        tmp, w1, b1, nullptr, ff, TOKENS, DFF, D);
    // out = x2 + ff @ W2 + b2
    gemm_f16<1><<<dim3(D / BN, TOKENS / BM), 256>>>(
        ff, w2, b2, x2, (float*)d_out, TOKENS, D, DFF);
}

// round 14
// speedup vs baseline: 2.1590x; 1.1602x over previous
#include <cuda_runtime.h>
#include <cuda_fp16.h>
#include <math.h>
#include <stdint.h>

using f16 = __half;

// Problem constants
constexpr int TOKENS = 4 * 4096;   // 16384
constexpr int D      = 1024;
constexpr int DFF    = 4096;

// ---------------------------------------------------------------------------
// Static device scratch — activations fp16, residual path exact fp32
// ---------------------------------------------------------------------------
__device__ f16   g_tmp [(size_t)TOKENS * D];        // LN output (reused for LN2)
__device__ f16   g_qkv [(size_t)TOKENS * 3 * D];    // q|k|v per token
__device__ f16   g_attn[(size_t)TOKENS * D];        // attention output
__device__ float g_x2  [(size_t)TOKENS * D];        // x + attn@Wo + bo (exact fp32)
__device__ f16   g_ff  [(size_t)TOKENS * DFF];      // gelu(tmp@W1+b1)
__device__ f16   g_wqkv[(size_t)3 * D * D];         // [3D, D]  (N,K layout)
__device__ f16   g_wo  [(size_t)D * D];
__device__ f16   g_w1  [(size_t)DFF * D];
__device__ f16   g_w2  [(size_t)D * DFF];

// ---------------------------------------------------------------------------
// PTX helpers
// ---------------------------------------------------------------------------
__device__ __forceinline__ void ldsm4(uint32_t& r0, uint32_t& r1, uint32_t& r2,
                                      uint32_t& r3, const void* p) {
    uint32_t a = (uint32_t)__cvta_generic_to_shared(p);
    asm volatile("ldmatrix.sync.aligned.m8n8.x4.shared.b16 {%0,%1,%2,%3}, [%4];\n"
                 : "=r"(r0), "=r"(r1), "=r"(r2), "=r"(r3) : "r"(a));
}

__device__ __forceinline__ void mma16816(float c[4], uint32_t a0, uint32_t a1,
                                         uint32_t a2, uint32_t a3,
                                         uint32_t b0, uint32_t b1) {
    asm volatile(
        "mma.sync.aligned.m16n8k16.row.col.f32.f16.f16.f32 "
        "{%0,%1,%2,%3}, {%4,%5,%6,%7}, {%8,%9}, {%0,%1,%2,%3};\n"
        : "+f"(c[0]), "+f"(c[1]), "+f"(c[2]), "+f"(c[3])
        : "r"(a0), "r"(a1), "r"(a2), "r"(a3), "r"(b0), "r"(b1));
}

__device__ __forceinline__ void cpa16(const void* smem, const void* gmem) {
    uint32_t a = (uint32_t)__cvta_generic_to_shared(smem);
    asm volatile("cp.async.cg.shared.global [%0], [%1], 16;\n" :: "r"(a), "l"(gmem) : "memory");
}
#define CP_COMMIT() asm volatile("cp.async.commit_group;\n" ::: "memory")

// ---------------------------------------------------------------------------
// Weight transpose + fp32->fp16 convert:  W[K,N] -> Wt[N,K]
// ---------------------------------------------------------------------------
__global__ void transpose_cvt(const float* __restrict__ W, f16* __restrict__ Wt,
                              int K, int N) {
    __shared__ float t[32][33];
    int n0 = blockIdx.x * 32, k0 = blockIdx.y * 32;
    #pragma unroll
    for (int r = threadIdx.y; r < 32; r += 8)
        t[r][threadIdx.x] = W[(size_t)(k0 + r) * N + n0 + threadIdx.x];
    __syncthreads();
    #pragma unroll
    for (int r = threadIdx.y; r < 32; r += 8)
        Wt[(size_t)(n0 + r) * K + k0 + threadIdx.x] = __float2half_rn(t[threadIdx.x][r]);
}

// ---------------------------------------------------------------------------
// LayerNorm (fp32 in -> fp16 out), one block per row of 1024
// ---------------------------------------------------------------------------
__global__ void __launch_bounds__(256) ln_kernel(const float* __restrict__ x,
                                                 const float* __restrict__ g,
                                                 const float* __restrict__ b,
                                                 f16* __restrict__ out) {
    const int row = blockIdx.x;
    const int tid = threadIdx.x;
    const float4 v = reinterpret_cast<const float4*>(x + (size_t)row * D)[tid];
    float s  = v.x + v.y + v.z + v.w;
    float ss = v.x * v.x + v.y * v.y + v.z * v.z + v.w * v.w;
    #pragma unroll
    for (int o = 16; o; o >>= 1) {
        s  += __shfl_xor_sync(0xffffffffu, s, o);
        ss += __shfl_xor_sync(0xffffffffu, ss, o);
    }
    __shared__ float sh[16];
    const int warp = tid >> 5, lane = tid & 31;
    if (lane == 0) { sh[warp] = s; sh[warp + 8] = ss; }
    __syncthreads();
    float ts = 0.f, tss = 0.f;
    #pragma unroll
    for (int w = 0; w < 8; ++w) { ts += sh[w]; tss += sh[w + 8]; }
    const float mu = ts * (1.0f / D);
    const float var = tss * (1.0f / D) - mu * mu;
    const float rs = rsqrtf(var + 1e-5f);
    const float4 gg = reinterpret_cast<const float4*>(g)[tid];
    const float4 bb = reinterpret_cast<const float4*>(b)[tid];
    __half2* o2 = reinterpret_cast<__half2*>(out + (size_t)row * D);
    o2[tid * 2 + 0] = __floats2half2_rn((v.x - mu) * rs * gg.x + bb.x,
                                        (v.y - mu) * rs * gg.y + bb.y);
    o2[tid * 2 + 1] = __floats2half2_rn((v.z - mu) * rs * gg.z + bb.z,
                                        (v.w - mu) * rs * gg.w + bb.w);
}

// ---------------------------------------------------------------------------
// Per-token head-mixing attention (fp16 in -> fp16 out, fp32 math).
// ---------------------------------------------------------------------------
__global__ void __launch_bounds__(64) attn_kernel(const f16* __restrict__ qkv,
                                                  const float* __restrict__ unc,
                                                  f16* __restrict__ out) {
    const int tok = blockIdx.x;
    const int i = threadIdx.x;
    __shared__ float ks[16][64];
    __shared__ float vs[16][64];
    const f16* base = qkv + (size_t)tok * (3 * D);

    float qi[16];
    #pragma unroll
    for (int h = 0; h < 16; ++h) {
        ks[h][i] = __half2float(base[D + h * 64 + i]);
        vs[h][i] = __half2float(base[2 * D + h * 64 + i]);
        qi[h] = __half2float(base[h * 64 + i]);
    }
    float su = 0.f;
    #pragma unroll
    for (int h = 0; h < 16; ++h) su += unc[h];
    const float iscale = 1.0f / (8.0f * su);
    __syncthreads();

    float s[64];
    #pragma unroll
    for (int j = 0; j < 64; ++j) s[j] = 0.f;
    #pragma unroll
    for (int h = 0; h < 16; ++h) {
        const float qh = qi[h];
        const float4* kr = reinterpret_cast<const float4*>(&ks[h][0]);
        #pragma unroll
        for (int j4 = 0; j4 < 16; ++j4) {
            const float4 kv = kr[j4];
            s[j4 * 4 + 0] += qh * kv.x;
            s[j4 * 4 + 1] += qh * kv.y;
            s[j4 * 4 + 2] += qh * kv.z;
            s[j4 * 4 + 3] += qh * kv.w;
        }
    }
    float m = -1e30f;
    #pragma unroll
    for (int j = 0; j < 64; ++j) { s[j] *= iscale; m = fmaxf(m, s[j]); }
    float den = 0.f;
    #pragma unroll
    for (int j = 0; j < 64; ++j) { s[j] = expf(s[j] - m); den += s[j]; }
    const float dinv = 1.0f / den;

    f16* ob = out + (size_t)tok * D;
    #pragma unroll
    for (int h = 0; h < 16; ++h) {
        const float4* vr = reinterpret_cast<const float4*>(&vs[h][0]);
        float o = 0.f;
        #pragma unroll
        for (int j4 = 0; j4 < 16; ++j4) {
            const float4 vv = vr[j4];
            o += s[j4 * 4 + 0] * vv.x + s[j4 * 4 + 1] * vv.y +
                 s[j4 * 4 + 2] * vv.z + s[j4 * 4 + 3] * vv.w;
        }
        ob[h * 64 + i] = __float2half_rn(o * dinv);
    }
}

// ---------------------------------------------------------------------------
// Tiled FP16 GEMM (fp32 accum): C[M,N] = A[M,K] @ Bt[N,K]^T with epilogues.
// BM=128, BN=128, BK=32 halves, THREE-stage cp.async, ONE __syncthreads per
// k-step (compute-before-prefetch ordering; wait_group 1 keeps exactly the
// in-flight stage pending). 256 threads (8 warps as 2x4, warp tile 64x32),
// ldmatrix.x4 + m16n8k16, dynamic smem 60KB, 2 CTAs/SM.
// EPI 0: out fp16 = C
// EPI 1: out fp32 = C + bias + res     (exact residual path)
// EPI 2: out fp16 = gelu(C + bias)     (exact erf gelu)
// ---------------------------------------------------------------------------
constexpr int BM = 128, BN = 128, BK = 32, PAD = 8, STG = 3;
constexpr int SROWH = BK + PAD;                 // halves per smem row (40)
constexpr int A_ELE = BM * SROWH;               // halves per A stage (5120)
constexpr int B_ELE = BN * SROWH;
constexpr size_t GEMM_SMEM = (size_t)STG * (A_ELE + B_ELE) * 2;  // 61440 B

template <int EPI>
__global__ void __launch_bounds__(256, 2) gemm_f16(
    const f16* __restrict__ A, const f16* __restrict__ Bt,
    const float* __restrict__ bias, const float* __restrict__ res,
    void* __restrict__ out, int M, int N, int K) {
    extern __shared__ f16 smh[];
    f16* As = smh;                    // [STG][BM][SROWH]
    f16* Bs = smh + STG * A_ELE;      // [STG][BN][SROWH]

    const int tid = threadIdx.x;
    const int lane = tid & 31;
    const int warp = tid >> 5;
    const int wr = warp >> 2;       // 0..1 (M)
    const int wc = warp & 3;        // 0..3 (N)
    const int bm = blockIdx.y * BM;
    const int bn = blockIdx.x * BN;

    // cp.async mapping: each thread loads one row-half (16 halves = 2x16B)
    const int lrow = tid >> 1;
    const int lch = (tid & 1) * 16;
    const f16* Ag = A + (size_t)(bm + lrow) * K + lch;
    const f16* Bg = Bt + (size_t)(bn + lrow) * K + lch;
    f16* AsRow = As + lrow * SROWH + lch;
    f16* BsRow = Bs + lrow * SROWH + lch;

    float acc[4][4][4];
    #pragma unroll
    for (int i = 0; i < 4; ++i)
        #pragma unroll
        for (int j = 0; j < 4; ++j)
            #pragma unroll
            for (int k = 0; k < 4; ++k) acc[i][j][k] = 0.f;

    auto load_stage = [&](int buf, int kt) {
        const f16* a = Ag + kt * BK;
        f16* as = AsRow + buf * A_ELE;
        cpa16(as, a);
        cpa16(as + 8, a + 8);
        const f16* b = Bg + kt * BK;
        f16* bs = BsRow + buf * B_ELE;
        cpa16(bs, b);
        cpa16(bs + 8, b + 8);
    };

    const int KT = K / BK;
    load_stage(0, 0); CP_COMMIT();
    load_stage(1, 1); CP_COMMIT();

    for (int kt = 0; kt < KT; ++kt) {
        const int buf = kt % 3;
        // stage kt must be resident; leave the newest commit in flight
        asm volatile("cp.async.wait_group 1;\n" ::: "memory");
        __syncthreads();

        const f16* Ab = As + (size_t)buf * A_ELE;
        const f16* Bb = Bs + (size_t)buf * B_ELE;
        #pragma unroll
        for (int kk = 0; kk < 2; ++kk) {     // two k16 chunks in BK=32
            uint32_t af[4][4];
            #pragma unroll
            for (int mi = 0; mi < 4; ++mi) {
                const int r = wr * 64 + mi * 16 + (lane & 15);
                const int c = kk * 16 + (lane >> 4) * 8;
                ldsm4(af[mi][0], af[mi][1], af[mi][2], af[mi][3],
                      Ab + (size_t)r * SROWH + c);
            }
            uint32_t bfr[2][4];
            #pragma unroll
            for (int nj = 0; nj < 2; ++nj) {  // covers n-tiles 2nj, 2nj+1
                const int l8 = lane & 7;
                const int q = lane >> 3;      // 0..3
                const int n = wc * 32 + nj * 16 + (q >> 1) * 8 + l8;
                const int c = kk * 16 + (q & 1) * 8;
                ldsm4(bfr[nj][0], bfr[nj][1], bfr[nj][2], bfr[nj][3],
                      Bb + (size_t)n * SROWH + c);
            }
            #pragma unroll
            for (int mi = 0; mi < 4; ++mi)
                #pragma unroll
                for (int ni = 0; ni < 4; ++ni)
                    mma16816(acc[mi][ni], af[mi][0], af[mi][1], af[mi][2], af[mi][3],
                             bfr[ni >> 1][(ni & 1) * 2], bfr[ni >> 1][(ni & 1) * 2 + 1]);
        }

        // prefetch stage kt+2 into buffer (kt+2)%3 — safe: all warps passed the
        // sync above, which follows every warp's compute on that buffer (iter kt-1)
        if (kt + 2 < KT) {
            load_stage((kt + 2) % 3, kt + 2);
            CP_COMMIT();
        } else {
            CP_COMMIT();   // keep group accounting uniform for wait_group 1
        }
    }

    // Epilogue
    #pragma unroll
    for (int mi = 0; mi < 4; ++mi) {
        #pragma unroll
        for (int ni = 0; ni < 4; ++ni) {
            const int row = bm + wr * 64 + mi * 16 + (lane >> 2);
            const int col = bn + wc * 32 + ni * 8 + (lane & 3) * 2;
            const float c0 = acc[mi][ni][0], c1 = acc[mi][ni][1];
            const float c2 = acc[mi][ni][2], c3 = acc[mi][ni][3];
            if (EPI == 0) {
                f16* o = (f16*)out;
                *(__half2*)(o + (size_t)row * N + col) = __floats2half2_rn(c0, c1);
                *(__half2*)(o + (size_t)(row + 8) * N + col) = __floats2half2_rn(c2, c3);
            } else if (EPI == 1) {
                const float bz0 = bias[col], bz1 = bias[col + 1];
                const float* r0 = res + (size_t)row * N + col;
                const float* r1 = res + (size_t)(row + 8) * N + col;
                float* o = (float*)out;
                *(float2*)(o + (size_t)row * N + col) =
                    make_float2(c0 + bz0 + r0[0], c1 + bz1 + r0[1]);
                *(float2*)(o + (size_t)(row + 8) * N + col) =
                    make_float2(c2 + bz0 + r1[0], c3 + bz1 + r1[1]);
            } else {
                const float bz0 = bias[col], bz1 = bias[col + 1];
                auto gelu = [](float v) { return 0.5f * v * (1.0f + erff(v * 0.70710678118654752f)); };
                f16* o = (f16*)out;
                *(__half2*)(o + (size_t)row * N + col) =
                    __floats2half2_rn(gelu(c0 + bz0), gelu(c1 + bz1));
                *(__half2*)(o + (size_t)(row + 8) * N + col) =
                    __floats2half2_rn(gelu(c2 + bz0), gelu(c3 + bz1));
            }
        }
    }
}

// ---------------------------------------------------------------------------
// Launch
// ---------------------------------------------------------------------------
extern "C" void kernel_launch(void* const* d_in, const int* in_sizes, int n_in,
                              void* d_out, int out_size) {
    const float* x    = (const float*)d_in[0];
    const float* unc  = (const float*)d_in[1];
    const float* Wq   = (const float*)d_in[2];
    const float* Wk   = (const float*)d_in[3];
    const float* Wv   = (const float*)d_in[4];
    const float* Wo   = (const float*)d_in[5];
    const float* bo   = (const float*)d_in[6];
    const float* ln1g = (const float*)d_in[7];
    const float* ln1b = (const float*)d_in[8];
    const float* ln2g = (const float*)d_in[9];
    const float* ln2b = (const float*)d_in[10];
    const float* W1   = (const float*)d_in[11];
    const float* b1   = (const float*)d_in[12];
    const float* W2   = (const float*)d_in[13];
    const float* b2   = (const float*)d_in[14];

    f16 *tmp, *qkv, *attn, *ff, *wqkv, *wo, *w1, *w2;
    float* x2;
    cudaGetSymbolAddress((void**)&tmp, g_tmp);
    cudaGetSymbolAddress((void**)&qkv, g_qkv);
    cudaGetSymbolAddress((void**)&attn, g_attn);
    cudaGetSymbolAddress((void**)&x2, g_x2);
    cudaGetSymbolAddress((void**)&ff, g_ff);
    cudaGetSymbolAddress((void**)&wqkv, g_wqkv);
    cudaGetSymbolAddress((void**)&wo, g_wo);
    cudaGetSymbolAddress((void**)&w1, g_w1);
    cudaGetSymbolAddress((void**)&w2, g_w2);

    cudaFuncSetAttribute(gemm_f16<0>, cudaFuncAttributeMaxDynamicSharedMemorySize, (int)GEMM_SMEM);
    cudaFuncSetAttribute(gemm_f16<1>, cudaFuncAttributeMaxDynamicSharedMemorySize, (int)GEMM_SMEM);
    cudaFuncSetAttribute(gemm_f16<2>, cudaFuncAttributeMaxDynamicSharedMemorySize, (int)GEMM_SMEM);

    const dim3 tb(32, 8);
    transpose_cvt<<<dim3(D / 32, D / 32), tb>>>(Wq, wqkv, D, D);
    transpose_cvt<<<dim3(D / 32, D / 32), tb>>>(Wk, wqkv + (size_t)D * D, D, D);
    transpose_cvt<<<dim3(D / 32, D / 32), tb>>>(Wv, wqkv + (size_t)2 * D * D, D, D);
    transpose_cvt<<<dim3(D / 32, D / 32), tb>>>(Wo, wo, D, D);
    transpose_cvt<<<dim3(DFF / 32, D / 32), tb>>>(W1, w1, D, DFF);
    transpose_cvt<<<dim3(D / 32, DFF / 32), tb>>>(W2, w2, DFF, D);

    // tmp = LN1(x)
    ln_kernel<<<TOKENS, 256>>>(x, ln1g, ln1b, tmp);
    // qkv = tmp @ [Wq|Wk|Wv]
    gemm_f16<0><<<dim3(3 * D / BN, TOKENS / BM), 256, GEMM_SMEM>>>(
        tmp, wqkv, nullptr, nullptr, qkv, TOKENS, 3 * D, D);
    // per-token attention
    attn_kernel<<<TOKENS, 64>>>(qkv, unc, attn);
    // x2 = x + attn @ Wo + bo
    gemm_f16<1><<<dim3(D / BN, TOKENS / BM), 256, GEMM_SMEM>>>(
        attn, wo, bo, x, x2, TOKENS, D, D);
    // tmp = LN2(x2)
    ln_kernel<<<TOKENS, 256>>>(x2, ln2g, ln2b, tmp);
    // ff = gelu(tmp @ W1 + b1)
    gemm_f16<2><<<dim3(DFF / BN, TOKENS / BM), 256, GEMM_SMEM>>>(
        tmp, w1, b1, nullptr, ff, TOKENS, DFF, D);
    // out = x2 + ff @ W2 + b2
    gemm_f16<1><<<dim3(D / BN, TOKENS / BM), 256, GEMM_SMEM>>>(
        ff, w2, b2, x2, (float*)d_out, TOKENS, D, DFF);
}